// round 12
// baseline (speedup 1.0000x reference)
#include <cuda_runtime.h>
#include <math.h>

// ChebyshevDescriptor — 4 threads/atom + packed f32x2 (FFMA2) pair math.
// N=20000, K=24, out [N,52] = [rad_un17 | rad_w17 | ang_un9 | ang_w9].
//
// kernel 1: pack positions+typespin into float4 table (__device__ global).
// kernel 2: subthread s (0..3) owns neighbors j = 6s+m (m=0..5): gathers
// (1 LDG.128 each), radial sums in registers, stages (ux,uy,uz,ws) as
// sliding-window float2 arrays in shared: win[k] = {v_k, v_{(k+1)%24}} so an
// aligned LDS.64 at any k yields two consecutive partners. Angular pairs
// by rotation (j, j+r mod 24) processed as duos (r, r+1), r=1..12, with
// fma.rn.f32x2 (one slot = two FMAs); the r=12/j>=12 overcount is killed by
// zeroing the duo's hi weight. Quad-reduce via 2 butterfly shuffles.
//
// R11 delta vs the audited R5 source: __launch_bounds__(BT, 9) guarantees
// 9 blocks/SM residency (grid 1250 -> single wave at <=113 regs).

#define N_ATOMS 20000
#define KNBR    24
#define RAD_CUT 8.0f
#define ANG_CUT 6.5f
#define MIN_CUT 0.55f
#define BT      64
#define APB     16
#define ASTR    200   // floats/atom in shared: 4 windows x 48 + 8 pad

typedef unsigned long long ull;

__device__ __forceinline__ ull pk2(float lo, float hi) {
    ull r; asm("mov.b64 %0, {%1,%2};" : "=l"(r) : "f"(lo), "f"(hi)); return r;
}
__device__ __forceinline__ void upk2(ull v, float& lo, float& hi) {
    asm("mov.b64 {%0,%1}, %2;" : "=f"(lo), "=f"(hi) : "l"(v));
}
__device__ __forceinline__ ull f2fma(ull a, ull b, ull c) {
    ull d; asm("fma.rn.f32x2 %0, %1, %2, %3;" : "=l"(d) : "l"(a), "l"(b), "l"(c)); return d;
}
__device__ __forceinline__ ull f2mul(ull a, ull b) {
    ull d; asm("mul.rn.f32x2 %0, %1, %2;" : "=l"(d) : "l"(a), "l"(b)); return d;
}
__device__ __forceinline__ ull f2add(ull a, ull b) {
    ull d; asm("add.rn.f32x2 %0, %1, %2;" : "=l"(d) : "l"(a), "l"(b)); return d;
}

__device__ float4 g_pos4[N_ATOMS];   // (x, y, z, typespin)

__global__ void pack_kernel(const float* __restrict__ pos, const int* __restrict__ spec) {
    const int i = blockIdx.x * blockDim.x + threadIdx.x;
    if (i < N_ATOMS)
        g_pos4[i] = make_float4(pos[3 * i], pos[3 * i + 1], pos[3 * i + 2],
                                spec[i] ? 1.0f : -1.0f);
}

__global__ __launch_bounds__(BT, 9)
void cheb_kernel(const int* __restrict__ nbr, float* __restrict__ out) {
    __shared__ __align__(16) float s_w[APB][ASTR];

    const int t = threadIdx.x;
    const int s = t & 3;
    const int a = t >> 2;
    const int atom = blockIdx.x * APB + a;    // 1250 * 16 == 20000 exactly

    float* wb = s_w[a];                       // windows: x @0, y @48, z @96, w @144

    const float4 me = g_pos4[atom];

    // ---------------- pass 1: gather own 6 (consecutive) neighbors + radial ----------------
    float ru[17], rw[17];
    #pragma unroll
    for (int q = 0; q < 17; q++) { ru[q] = 0.0f; rw[q] = 0.0f; }

    float4 myu[6];

    // neighbor ids j = 6s..6s+5: byte offset 96*atom + 24*s -> 8B aligned
    const int2* nb2 = (const int2*)(nbr + atom * KNBR + 6 * s);
    const int2 n01 = nb2[0], n23 = nb2[1], n45 = nb2[2];
    const int nj[6] = {n01.x, n01.y, n23.x, n23.y, n45.x, n45.y};

    #pragma unroll
    for (int m = 0; m < 6; m++) {
        const int j = 6 * s + m;
        const float4 p = g_pos4[nj[m]];
        const float dx = p.x - me.x, dy = p.y - me.y, dz = p.z - me.z;
        const float d2 = dx * dx + dy * dy + dz * dz;
        const float inv = rsqrtf(fmaxf(d2, 1e-18f));
        const float d = d2 * inv;
        const float sj = p.w;

        const bool mr = (d <= RAD_CUT) && (d > MIN_CUT);
        const float fc = 0.5f * (__cosf(d * (3.14159265358979f / RAD_CUT)) + 1.0f);
        const float wr  = mr ? fc : 0.0f;
        const float wrs = wr * sj;
        const float x = mr ? (2.0f * (d - MIN_CUT) * (1.0f / (RAD_CUT - MIN_CUT)) - 1.0f)
                           : 0.0f;

        const bool ma = (d <= ANG_CUT) && (d > MIN_CUT);
        const float fca = 0.5f * (__cosf(d * (3.14159265358979f / ANG_CUT)) + 1.0f);
        const float wa = ma ? fca : 0.0f;

        const float ux = dx * inv, uy = dy * inv, uz = dz * inv, ws = wa * sj;
        myu[m] = make_float4(ux, uy, uz, ws);

        // sliding-window stores: win[j].lo = v, win[(j-1) mod 24].hi = v
        const int jw = (j == 0) ? 23 : (j - 1);
        wb[      2 * j] = ux;  wb[      2 * jw + 1] = ux;
        wb[ 48 + 2 * j] = uy;  wb[ 48 + 2 * jw + 1] = uy;
        wb[ 96 + 2 * j] = uz;  wb[ 96 + 2 * jw + 1] = uz;
        wb[144 + 2 * j] = ws;  wb[144 + 2 * jw + 1] = ws;

        // radial accumulate
        ru[0] += wr;        rw[0] += wrs;
        ru[1] += wr * x;    rw[1] += wrs * x;
        const float x2 = x + x;
        float Tmm = 1.0f, Tm = x;
        #pragma unroll
        for (int q = 2; q < 17; q++) {
            const float T = x2 * Tm - Tmm;
            ru[q] += wr * T;
            rw[q] += wrs * T;
            Tmm = Tm; Tm = T;
        }
    }

    // quad-reduce radial (lanes of a quad differ in bits 0..1)
    #pragma unroll
    for (int q = 0; q < 17; q++) {
        ru[q] += __shfl_xor_sync(0xffffffffu, ru[q], 1);
        ru[q] += __shfl_xor_sync(0xffffffffu, ru[q], 2);
        rw[q] += __shfl_xor_sync(0xffffffffu, rw[q], 1);
        rw[q] += __shfl_xor_sync(0xffffffffu, rw[q], 2);
    }

    float* o = out + (size_t)atom * 52;   // 208B -> 16B-aligned
    if (s == 0) {
        ((float4*)o)[0] = make_float4(ru[0],  ru[1],  ru[2],  ru[3]);
        ((float4*)o)[1] = make_float4(ru[4],  ru[5],  ru[6],  ru[7]);
        ((float4*)o)[2] = make_float4(ru[8],  ru[9],  ru[10], ru[11]);
        ((float4*)o)[3] = make_float4(ru[12], ru[13], ru[14], ru[15]);
        ((float4*)o)[4] = make_float4(ru[16], rw[0],  rw[1],  rw[2]);
        ((float4*)o)[5] = make_float4(rw[3],  rw[4],  rw[5],  rw[6]);
        ((float4*)o)[6] = make_float4(rw[7],  rw[8],  rw[9],  rw[10]);
        ((float4*)o)[7] = make_float4(rw[11], rw[12], rw[13], rw[14]);
        ((float2*)o)[16] = make_float2(rw[15], rw[16]);   // out[32..33]
    }

    __syncwarp();   // windows visible to quad partners (same warp)

    // ---------------- pass 2: angular duos, packed f32x2 ----------------
    const ull NEG1 = 0xBF800000BF800000ull;   // (-1.f, -1.f)
    ull aU[9], aW[9];
    #pragma unroll
    for (int q = 0; q < 9; q++) { aU[q] = 0ull; aW[q] = 0ull; }   // (0.f, 0.f)

    #pragma unroll
    for (int m = 0; m < 6; m++) {
        const float4 av = myu[m];
        const ull ax2 = pk2(av.x, av.x);
        const ull ay2 = pk2(av.y, av.y);
        const ull az2 = pk2(av.z, av.z);
        const ull aw2 = pk2(av.w, av.w);
        const int jm = 6 * s + m;

        #pragma unroll
        for (int duo = 0; duo < 6; duo++) {
            int k = jm + 2 * duo + 1;        // duo covers rotations (2duo+1, 2duo+2)
            if (k >= KNBR) k -= KNBR;        // window gives {v_k, v_{k+1 mod 24}}
            const ull bx2 = *(const ull*)(wb +       2 * k);
            const ull by2 = *(const ull*)(wb +  48 + 2 * k);
            const ull bz2 = *(const ull*)(wb +  96 + 2 * k);
            ull       bw2 = *(const ull*)(wb + 144 + 2 * k);
            // r=12 exists only for j<12: mask hi half of the last duo otherwise
            if (duo == 5 && jm >= 12) bw2 &= 0x00000000FFFFFFFFull;

            const ull ws2 = f2mul(aw2, bw2);             // packed (wa_j sj)(wa_k sk)
            const ull wp2 = ws2 & 0x7FFFFFFF7FFFFFFFull; // packed wa_j wa_k
            const ull ct2 = f2fma(az2, bz2, f2fma(ay2, by2, f2mul(ax2, bx2)));
            const ull c2t2 = f2add(ct2, ct2);

            aU[0] = f2add(aU[0], wp2);
            aW[0] = f2add(aW[0], ws2);
            aU[1] = f2fma(wp2, ct2, aU[1]);
            aW[1] = f2fma(ws2, ct2, aW[1]);
            ull Tm2 = ct2, mTmm2 = NEG1;                 // carry (T_{q-1}, -T_{q-2})
            #pragma unroll
            for (int q = 2; q < 9; q++) {
                const ull T2 = f2fma(c2t2, Tm2, mTmm2);  // T_q = 2ct*T_{q-1} - T_{q-2}
                aU[q] = f2fma(wp2, T2, aU[q]);
                aW[q] = f2fma(ws2, T2, aW[q]);
                if (q < 8) mTmm2 = f2mul(Tm2, NEG1);     // foldable negate
                Tm2 = T2;
            }
        }
    }

    // quad-reduce packed accumulators
    #pragma unroll
    for (int q = 0; q < 9; q++) {
        aU[q] = f2add(aU[q], __shfl_xor_sync(0xffffffffu, aU[q], 1));
        aU[q] = f2add(aU[q], __shfl_xor_sync(0xffffffffu, aU[q], 2));
        aW[q] = f2add(aW[q], __shfl_xor_sync(0xffffffffu, aW[q], 1));
        aW[q] = f2add(aW[q], __shfl_xor_sync(0xffffffffu, aW[q], 2));
    }

    if (s == 0) {   // horizontal add of packed halves, then store out[34..51]
        float uf[9], wf[9], lo, hi;
        #pragma unroll
        for (int q = 0; q < 9; q++) {
            upk2(aU[q], lo, hi); uf[q] = lo + hi;
            upk2(aW[q], lo, hi); wf[q] = lo + hi;
        }
        float2* o2 = (float2*)(o + 34);   // 8B-aligned
        o2[0] = make_float2(uf[0], uf[1]);
        o2[1] = make_float2(uf[2], uf[3]);
        o2[2] = make_float2(uf[4], uf[5]);
        o2[3] = make_float2(uf[6], uf[7]);
        o2[4] = make_float2(uf[8], wf[0]);
        o2[5] = make_float2(wf[1], wf[2]);
        o2[6] = make_float2(wf[3], wf[4]);
        o2[7] = make_float2(wf[5], wf[6]);
        o2[8] = make_float2(wf[7], wf[8]);
    }
}

extern "C" void kernel_launch(void* const* d_in, const int* in_sizes, int n_in,
                              void* d_out, int out_size) {
    const float* positions  = (const float*)d_in[0];
    const int* species_idx  = (const int*)d_in[1];
    const int* neighbor_idx = (const int*)d_in[2];
    float* out = (float*)d_out;

    pack_kernel<<<(N_ATOMS + 255) / 256, 256>>>(positions, species_idx);
    cheb_kernel<<<N_ATOMS / APB, BT>>>(neighbor_idx, out);
}

// round 13
// speedup vs baseline: 1.1773x; 1.1773x over previous
#include <cuda_runtime.h>
#include <math.h>

// ChebyshevDescriptor — 8 threads per atom, SINGLE kernel (R8 structure with
// inline gathers; the separate pack_kernel cost ~2.5us of launch overhead).
// N=20000, K=24, out [N,52] = [rad_un17 | rad_w17 | ang_un9 | ang_w9].
//
// Subthread s (0..7) of an atom owns neighbors j = s+8m (m=0..2): gathers
// pos/spec directly, radial partials in registers, stages (ux,uy,uz,ws) to a
// per-atom shared float4 table (also kept in regs). Angular pairs by rotation
// (j, (j+r) mod 24): r=1..11 all owned j, r=12 for owned j<12 -> 276 total.
// Octet reduction = 3 butterfly shuffles; lane s==0 stores vectorized.
// (R10's column-reduce variant measured WORSE than butterflies — reverted.)

#define N_ATOMS 20000
#define KNBR    24
#define RAD_CUT 8.0f
#define ANG_CUT 6.5f
#define MIN_CUT 0.55f
#define BT      64
#define APB     8            // atoms per block
#define SSTR    25           // padded float4 stride

__global__ __launch_bounds__(BT, 17)
void cheb_kernel(const float* __restrict__ pos,
                 const int* __restrict__ spec,
                 const int* __restrict__ nbr,
                 float* __restrict__ out) {
    __shared__ float4 s_u4[APB][SSTR];    // 3.2 KB

    const int t = threadIdx.x;
    const int s = t & 7;                  // subthread within octet
    const int a = t >> 3;                 // atom within block
    const int atom = blockIdx.x * APB + a;    // 2500 * 8 == 20000 exactly

    const float px = pos[3 * atom + 0];
    const float py = pos[3 * atom + 1];
    const float pz = pos[3 * atom + 2];

    // ---------------- pass 1: gather own 3 neighbors + radial partials ----------------
    float ru[17], rw[17];
    #pragma unroll
    for (int q = 0; q < 17; q++) { ru[q] = 0.0f; rw[q] = 0.0f; }

    float4 myu[3];

    #pragma unroll
    for (int m = 0; m < 3; m++) {
        const int j = s + 8 * m;
        const int nj = nbr[atom * KNBR + j];
        const float dx = pos[3 * nj + 0] - px;
        const float dy = pos[3 * nj + 1] - py;
        const float dz = pos[3 * nj + 2] - pz;
        const float sj = spec[nj] ? 1.0f : -1.0f;    // TYPESPIN = [-1, 1]
        const float d2 = dx * dx + dy * dy + dz * dz;
        const float inv = rsqrtf(fmaxf(d2, 1e-18f));
        const float d = d2 * inv;

        const bool mr = (d <= RAD_CUT) && (d > MIN_CUT);
        const float fc = 0.5f * (__cosf(d * (3.14159265358979f / RAD_CUT)) + 1.0f);
        const float wr  = mr ? fc : 0.0f;
        const float wrs = wr * sj;
        const float x = mr ? (2.0f * (d - MIN_CUT) * (1.0f / (RAD_CUT - MIN_CUT)) - 1.0f)
                           : 0.0f;   // weight 0 when masked; x=0 keeps T bounded

        const bool ma = (d <= ANG_CUT) && (d > MIN_CUT);
        const float fca = 0.5f * (__cosf(d * (3.14159265358979f / ANG_CUT)) + 1.0f);
        const float wa = ma ? fca : 0.0f;

        const float4 u = make_float4(dx * inv, dy * inv, dz * inv, wa * sj);
        myu[m] = u;
        s_u4[a][j] = u;

        ru[0] += wr;        rw[0] += wrs;
        ru[1] += wr * x;    rw[1] += wrs * x;
        const float x2 = x + x;
        float Tmm = 1.0f, Tm = x;
        #pragma unroll
        for (int q = 2; q < 17; q++) {
            const float T = x2 * Tm - Tmm;
            ru[q] += wr * T;
            rw[q] += wrs * T;
            Tmm = Tm; Tm = T;
        }
    }

    // octet-reduce radial (lanes of an atom differ in bits 0..2)
    #pragma unroll
    for (int q = 0; q < 17; q++) {
        ru[q] += __shfl_xor_sync(0xffffffffu, ru[q], 1);
        ru[q] += __shfl_xor_sync(0xffffffffu, ru[q], 2);
        ru[q] += __shfl_xor_sync(0xffffffffu, ru[q], 4);
        rw[q] += __shfl_xor_sync(0xffffffffu, rw[q], 1);
        rw[q] += __shfl_xor_sync(0xffffffffu, rw[q], 2);
        rw[q] += __shfl_xor_sync(0xffffffffu, rw[q], 4);
    }

    float* o = out + (size_t)atom * 52;   // 208B = 16*13 -> 16B-aligned
    if (s == 0) {
        ((float4*)o)[0] = make_float4(ru[0],  ru[1],  ru[2],  ru[3]);
        ((float4*)o)[1] = make_float4(ru[4],  ru[5],  ru[6],  ru[7]);
        ((float4*)o)[2] = make_float4(ru[8],  ru[9],  ru[10], ru[11]);
        ((float4*)o)[3] = make_float4(ru[12], ru[13], ru[14], ru[15]);
        ((float4*)o)[4] = make_float4(ru[16], rw[0],  rw[1],  rw[2]);
        ((float4*)o)[5] = make_float4(rw[3],  rw[4],  rw[5],  rw[6]);
        ((float4*)o)[6] = make_float4(rw[7],  rw[8],  rw[9],  rw[10]);
        ((float4*)o)[7] = make_float4(rw[11], rw[12], rw[13], rw[14]);
        ((float2*)o)[16] = make_float2(rw[15], rw[16]);   // out[32..33]
    }

    __syncwarp();   // staging visible: octet spans lanes of one warp only

    // ---------------- pass 2: angular, rotation pairs ----------------
    float aU[9], aW[9];
    #pragma unroll
    for (int q = 0; q < 9; q++) { aU[q] = 0.0f; aW[q] = 0.0f; }

    const float4* srow = &s_u4[a][0];

    #pragma unroll 1
    for (int r = 1; r <= 11; r++) {
        const int k0 = s + r;
        #pragma unroll
        for (int m = 0; m < 3; m++) {
            int k = k0 + 8 * m;
            if (k >= KNBR) k -= KNBR;
            const float4 av = myu[m];
            const float4 b = srow[k];

            const float wsp = av.w * b.w;     // (wa_j sj)(wa_k sk)
            const float wp  = fabsf(wsp);     // wa_j wa_k
            const float ct = av.x * b.x + av.y * b.y + av.z * b.z;   // |ct|<=1+ulp

            aU[0] += wp;        aW[0] += wsp;
            aU[1] += wp * ct;   aW[1] += wsp * ct;
            const float c2 = ct + ct;
            float Tmm = 1.0f, Tm = ct;
            #pragma unroll
            for (int q = 2; q < 9; q++) {
                const float T = c2 * Tm - Tmm;
                aU[q] += wp * T;
                aW[q] += wsp * T;
                Tmm = Tm; Tm = T;
            }
        }
    }
    {   // r = 12: owned j = s+8m < 12  ->  m <= 1 for s < 4, m == 0 for s >= 4
        const int mmax = (s < 4) ? 2 : 1;
        #pragma unroll 1
        for (int m = 0; m < mmax; m++) {
            int k = s + 12 + 8 * m;
            if (k >= KNBR) k -= KNBR;
            const float4 av = myu[m];
            const float4 b = srow[k];

            const float wsp = av.w * b.w;
            const float wp  = fabsf(wsp);
            const float ct = av.x * b.x + av.y * b.y + av.z * b.z;

            aU[0] += wp;        aW[0] += wsp;
            aU[1] += wp * ct;   aW[1] += wsp * ct;
            const float c2 = ct + ct;
            float Tmm = 1.0f, Tm = ct;
            #pragma unroll
            for (int q = 2; q < 9; q++) {
                const float T = c2 * Tm - Tmm;
                aU[q] += wp * T;
                aW[q] += wsp * T;
                Tmm = Tm; Tm = T;
            }
        }
    }

    // octet-reduce angular
    #pragma unroll
    for (int q = 0; q < 9; q++) {
        aU[q] += __shfl_xor_sync(0xffffffffu, aU[q], 1);
        aU[q] += __shfl_xor_sync(0xffffffffu, aU[q], 2);
        aU[q] += __shfl_xor_sync(0xffffffffu, aU[q], 4);
        aW[q] += __shfl_xor_sync(0xffffffffu, aW[q], 1);
        aW[q] += __shfl_xor_sync(0xffffffffu, aW[q], 2);
        aW[q] += __shfl_xor_sync(0xffffffffu, aW[q], 4);
    }

    if (s == 0) {   // out[34..51], 8B-aligned base -> float2 stores
        float2* o2 = (float2*)(o + 34);
        o2[0] = make_float2(aU[0], aU[1]);
        o2[1] = make_float2(aU[2], aU[3]);
        o2[2] = make_float2(aU[4], aU[5]);
        o2[3] = make_float2(aU[6], aU[7]);
        o2[4] = make_float2(aU[8], aW[0]);
        o2[5] = make_float2(aW[1], aW[2]);
        o2[6] = make_float2(aW[3], aW[4]);
        o2[7] = make_float2(aW[5], aW[6]);
        o2[8] = make_float2(aW[7], aW[8]);
    }
}

extern "C" void kernel_launch(void* const* d_in, const int* in_sizes, int n_in,
                              void* d_out, int out_size) {
    const float* positions  = (const float*)d_in[0];
    const int* species_idx  = (const int*)d_in[1];
    const int* neighbor_idx = (const int*)d_in[2];
    float* out = (float*)d_out;

    cheb_kernel<<<N_ATOMS / APB, BT>>>(positions, species_idx, neighbor_idx, out);
}

// round 14
// speedup vs baseline: 1.2210x; 1.0371x over previous
#include <cuda_runtime.h>
#include <math.h>

// ChebyshevDescriptor — 8 threads per atom, single kernel, BATCHED gathers.
// N=20000, K=24, out [N,52] = [rad_un17 | rad_w17 | ang_un9 | ang_w9].
//
// R13 delta vs R12: pass-1 gather is software-pipelined — all 3 neighbor
// indices load first, then all 12 data loads (9 pos + 3 spec) issue as one
// front-batched group (MLP~12), and only then does the radial math run.
// R12 interleaved the dependent loads with compute and exposed the latency
// (issue 63%->55% vs the packed-table two-kernel variant).
// Everything else identical: rotation pair enumeration, octet butterfly
// reductions, lane-0 vectorized stores.

#define N_ATOMS 20000
#define KNBR    24
#define RAD_CUT 8.0f
#define ANG_CUT 6.5f
#define MIN_CUT 0.55f
#define BT      64
#define APB     8            // atoms per block
#define SSTR    25           // padded float4 stride

__global__ __launch_bounds__(BT, 17)
void cheb_kernel(const float* __restrict__ pos,
                 const int* __restrict__ spec,
                 const int* __restrict__ nbr,
                 float* __restrict__ out) {
    __shared__ float4 s_u4[APB][SSTR];    // 3.2 KB

    const int t = threadIdx.x;
    const int s = t & 7;                  // subthread within octet
    const int a = t >> 3;                 // atom within block
    const int atom = blockIdx.x * APB + a;    // 2500 * 8 == 20000 exactly

    // ---------------- batched gather: indices, then all data loads ----------------
    int nj[3];
    #pragma unroll
    for (int m = 0; m < 3; m++)
        nj[m] = nbr[atom * KNBR + s + 8 * m];

    const float px = pos[3 * atom + 0];
    const float py = pos[3 * atom + 1];
    const float pz = pos[3 * atom + 2];

    float qx[3], qy[3], qz[3];
    int sp[3];
    #pragma unroll
    for (int m = 0; m < 3; m++) {
        qx[m] = pos[3 * nj[m] + 0];
        qy[m] = pos[3 * nj[m] + 1];
        qz[m] = pos[3 * nj[m] + 2];
        sp[m] = spec[nj[m]];
    }

    // ---------------- pass 1: radial partials (load-free compute) ----------------
    float ru[17], rw[17];
    #pragma unroll
    for (int q = 0; q < 17; q++) { ru[q] = 0.0f; rw[q] = 0.0f; }

    float4 myu[3];

    #pragma unroll
    for (int m = 0; m < 3; m++) {
        const int j = s + 8 * m;
        const float dx = qx[m] - px;
        const float dy = qy[m] - py;
        const float dz = qz[m] - pz;
        const float sj = sp[m] ? 1.0f : -1.0f;       // TYPESPIN = [-1, 1]
        const float d2 = dx * dx + dy * dy + dz * dz;
        const float inv = rsqrtf(fmaxf(d2, 1e-18f));
        const float d = d2 * inv;

        const bool mr = (d <= RAD_CUT) && (d > MIN_CUT);
        const float fc = 0.5f * (__cosf(d * (3.14159265358979f / RAD_CUT)) + 1.0f);
        const float wr  = mr ? fc : 0.0f;
        const float wrs = wr * sj;
        const float x = mr ? (2.0f * (d - MIN_CUT) * (1.0f / (RAD_CUT - MIN_CUT)) - 1.0f)
                           : 0.0f;   // weight 0 when masked; x=0 keeps T bounded

        const bool ma = (d <= ANG_CUT) && (d > MIN_CUT);
        const float fca = 0.5f * (__cosf(d * (3.14159265358979f / ANG_CUT)) + 1.0f);
        const float wa = ma ? fca : 0.0f;

        const float4 u = make_float4(dx * inv, dy * inv, dz * inv, wa * sj);
        myu[m] = u;
        s_u4[a][j] = u;

        ru[0] += wr;        rw[0] += wrs;
        ru[1] += wr * x;    rw[1] += wrs * x;
        const float x2 = x + x;
        float Tmm = 1.0f, Tm = x;
        #pragma unroll
        for (int q = 2; q < 17; q++) {
            const float T = x2 * Tm - Tmm;
            ru[q] += wr * T;
            rw[q] += wrs * T;
            Tmm = Tm; Tm = T;
        }
    }

    // octet-reduce radial (lanes of an atom differ in bits 0..2)
    #pragma unroll
    for (int q = 0; q < 17; q++) {
        ru[q] += __shfl_xor_sync(0xffffffffu, ru[q], 1);
        ru[q] += __shfl_xor_sync(0xffffffffu, ru[q], 2);
        ru[q] += __shfl_xor_sync(0xffffffffu, ru[q], 4);
        rw[q] += __shfl_xor_sync(0xffffffffu, rw[q], 1);
        rw[q] += __shfl_xor_sync(0xffffffffu, rw[q], 2);
        rw[q] += __shfl_xor_sync(0xffffffffu, rw[q], 4);
    }

    float* o = out + (size_t)atom * 52;   // 208B = 16*13 -> 16B-aligned
    if (s == 0) {
        ((float4*)o)[0] = make_float4(ru[0],  ru[1],  ru[2],  ru[3]);
        ((float4*)o)[1] = make_float4(ru[4],  ru[5],  ru[6],  ru[7]);
        ((float4*)o)[2] = make_float4(ru[8],  ru[9],  ru[10], ru[11]);
        ((float4*)o)[3] = make_float4(ru[12], ru[13], ru[14], ru[15]);
        ((float4*)o)[4] = make_float4(ru[16], rw[0],  rw[1],  rw[2]);
        ((float4*)o)[5] = make_float4(rw[3],  rw[4],  rw[5],  rw[6]);
        ((float4*)o)[6] = make_float4(rw[7],  rw[8],  rw[9],  rw[10]);
        ((float4*)o)[7] = make_float4(rw[11], rw[12], rw[13], rw[14]);
        ((float2*)o)[16] = make_float2(rw[15], rw[16]);   // out[32..33]
    }

    __syncwarp();   // staging visible: octet spans lanes of one warp only

    // ---------------- pass 2: angular, rotation pairs ----------------
    float aU[9], aW[9];
    #pragma unroll
    for (int q = 0; q < 9; q++) { aU[q] = 0.0f; aW[q] = 0.0f; }

    const float4* srow = &s_u4[a][0];

    #pragma unroll 1
    for (int r = 1; r <= 11; r++) {
        const int k0 = s + r;
        #pragma unroll
        for (int m = 0; m < 3; m++) {
            int k = k0 + 8 * m;
            if (k >= KNBR) k -= KNBR;
            const float4 av = myu[m];
            const float4 b = srow[k];

            const float wsp = av.w * b.w;     // (wa_j sj)(wa_k sk)
            const float wp  = fabsf(wsp);     // wa_j wa_k
            const float ct = av.x * b.x + av.y * b.y + av.z * b.z;   // |ct|<=1+ulp

            aU[0] += wp;        aW[0] += wsp;
            aU[1] += wp * ct;   aW[1] += wsp * ct;
            const float c2 = ct + ct;
            float Tmm = 1.0f, Tm = ct;
            #pragma unroll
            for (int q = 2; q < 9; q++) {
                const float T = c2 * Tm - Tmm;
                aU[q] += wp * T;
                aW[q] += wsp * T;
                Tmm = Tm; Tm = T;
            }
        }
    }
    {   // r = 12: owned j = s+8m < 12  ->  m <= 1 for s < 4, m == 0 for s >= 4
        const int mmax = (s < 4) ? 2 : 1;
        #pragma unroll 1
        for (int m = 0; m < mmax; m++) {
            int k = s + 12 + 8 * m;
            if (k >= KNBR) k -= KNBR;
            const float4 av = myu[m];
            const float4 b = srow[k];

            const float wsp = av.w * b.w;
            const float wp  = fabsf(wsp);
            const float ct = av.x * b.x + av.y * b.y + av.z * b.z;

            aU[0] += wp;        aW[0] += wsp;
            aU[1] += wp * ct;   aW[1] += wsp * ct;
            const float c2 = ct + ct;
            float Tmm = 1.0f, Tm = ct;
            #pragma unroll
            for (int q = 2; q < 9; q++) {
                const float T = c2 * Tm - Tmm;
                aU[q] += wp * T;
                aW[q] += wsp * T;
                Tmm = Tm; Tm = T;
            }
        }
    }

    // octet-reduce angular
    #pragma unroll
    for (int q = 0; q < 9; q++) {
        aU[q] += __shfl_xor_sync(0xffffffffu, aU[q], 1);
        aU[q] += __shfl_xor_sync(0xffffffffu, aU[q], 2);
        aU[q] += __shfl_xor_sync(0xffffffffu, aU[q], 4);
        aW[q] += __shfl_xor_sync(0xffffffffu, aW[q], 1);
        aW[q] += __shfl_xor_sync(0xffffffffu, aW[q], 2);
        aW[q] += __shfl_xor_sync(0xffffffffu, aW[q], 4);
    }

    if (s == 0) {   // out[34..51], 8B-aligned base -> float2 stores
        float2* o2 = (float2*)(o + 34);
        o2[0] = make_float2(aU[0], aU[1]);
        o2[1] = make_float2(aU[2], aU[3]);
        o2[2] = make_float2(aU[4], aU[5]);
        o2[3] = make_float2(aU[6], aU[7]);
        o2[4] = make_float2(aU[8], aW[0]);
        o2[5] = make_float2(aW[1], aW[2]);
        o2[6] = make_float2(aW[3], aW[4]);
        o2[7] = make_float2(aW[5], aW[6]);
        o2[8] = make_float2(aW[7], aW[8]);
    }
}

extern "C" void kernel_launch(void* const* d_in, const int* in_sizes, int n_in,
                              void* d_out, int out_size) {
    const float* positions  = (const float*)d_in[0];
    const int* species_idx  = (const int*)d_in[1];
    const int* neighbor_idx = (const int*)d_in[2];
    float* out = (float*)d_out;

    cheb_kernel<<<N_ATOMS / APB, BT>>>(positions, species_idx, neighbor_idx, out);
}